// round 2
// baseline (speedup 1.0000x reference)
#include <cuda_runtime.h>
#include <math.h>

#define M_TAGS   512
#define L_SEQ    4096
#define V_VOCAB  50000
#define VP1      50001
#define NCTA     64
#define CPC      8            // columns per CTA
#define MAIN_THREADS 256      // 8 warps, one per column
#define RING     4

// ---- device scratch (no allocations allowed) ----
__device__ float        g_abuf[RING * M_TAGS];   // ring of state vectors
__device__ float        g_ext[L_SEQ * M_TAGS];   // ext[t][j] = E[j, x[t]]
__device__ float        g_phipath;
__device__ unsigned int g_counter;

// =====================================================================
// Init kernel: alpha0, phi_path, ext gather, counter reset
// =====================================================================
__global__ void crf_init_kernel(const float* __restrict__ T,
                                const float* __restrict__ E,
                                const float* __restrict__ Eprev,
                                const float* __restrict__ Enext,
                                const float* __restrict__ Cap,
                                const int*   __restrict__ x,
                                const int*   __restrict__ y,
                                const int*   __restrict__ upper)
{
    const int b   = blockIdx.x;
    const int tid = threadIdx.x;

    if (b == 0) {
        // alpha0 = exp(phi0); counter = NCTA (meaning "alpha_0 is ready")
        const int x0 = x[0], x1 = x[1], u0 = upper[0];
        for (int m = tid; m < M_TAGS; m += blockDim.x) {
            float phi = T[M_TAGS * M_TAGS + m]          // T[M][m], row-major (M+1, M)
                      + Eprev[m * VP1 + M_TAGS]          // Eprev[m, B], B = M
                      + Enext[m * VP1 + x1]
                      + Cap[m * 2 + u0]
                      + E[m * V_VOCAB + x0];
            __stcg(&g_abuf[m], expf(phi));
        }
        if (tid == 0) g_counter = NCTA;
    } else if (b == 1) {
        // phi_path = sum over t of path potentials
        __shared__ float red[256];
        float acc = 0.f;
        for (int t = tid; t < L_SEQ; t += blockDim.x) {
            int yt = y[t];
            int yp = (t == 0)         ? M_TAGS : y[t - 1];
            int xp = (t == 0)         ? M_TAGS : x[t - 1];   // B == M_TAGS
            int xn = (t == L_SEQ - 1) ? M_TAGS : x[t + 1];
            acc += T[yp * M_TAGS + yt]
                 + Eprev[yt * VP1 + xp]
                 + Enext[yt * VP1 + xn]
                 + Cap[yt * 2 + upper[t]]
                 + E[yt * V_VOCAB + x[t]];
        }
        red[tid] = acc;
        __syncthreads();
        for (int s = 128; s > 0; s >>= 1) {
            if (tid < s) red[tid] += red[tid + s];
            __syncthreads();
        }
        if (tid == 0) g_phipath = red[0];
    } else {
        // ext gather: g_ext[t*512 + j] = E[j, x[t]]
        long long idx = (long long)(b - 2) * blockDim.x + tid;
        if (idx < (long long)L_SEQ * M_TAGS) {
            int t = (int)(idx >> 9);
            int j = (int)(idx & 511);
            g_ext[idx] = E[(long long)j * V_VOCAB + x[t]];
        }
    }
}

// =====================================================================
// Chain kernel: 4095 serial GEMV steps, 64 co-resident CTAs,
// lock-free sync through a single monotonic counter in L2.
// =====================================================================
__global__ void __launch_bounds__(MAIN_THREADS, 1)
crf_chain_kernel(const float* __restrict__ T, float* __restrict__ out)
{
    __shared__ float TmS[CPC * M_TAGS];   // TmS[w][i] = Tm[i][cta*8 + w]

    const int tid  = threadIdx.x;
    const int w    = tid >> 5;            // warp id = local column
    const int lane = tid & 31;
    const int cta  = blockIdx.x;
    const int jg   = cta * CPC + w;       // global column this warp owns
    const unsigned FULL = 0xffffffffu;

    // Stage Tm slice: coalesced (8 consecutive floats per row chunk)
    for (int idx = tid; idx < CPC * M_TAGS; idx += MAIN_THREADS) {
        int i  = idx >> 3;
        int wc = idx & 7;
        TmS[wc * M_TAGS + i] = T[i * M_TAGS + cta * CPC + wc];
    }
    __syncthreads();

    float ext_next = __ldg(&g_ext[1 * M_TAGS + jg]);  // ext for step 1
    float log_acc  = 0.f;                             // only (cta0, tid0) uses

    for (int t = 1; t < L_SEQ; ++t) {
        // ---- wait for alpha_{t-1} complete ----
        if (tid == 0) {
            const unsigned tgt = (unsigned)NCTA * (unsigned)t;
            while (*(volatile unsigned*)&g_counter < tgt) {}
        }
        __syncthreads();

        // ---- load full previous state (L2, bypass L1) ----
        const float* src = g_abuf + ((t - 1) & (RING - 1)) * M_TAGS;
        float a[16];
        #pragma unroll
        for (int k = 0; k < 16; ++k) a[k] = __ldcv(src + lane + 32 * k);

        // ---- dot with this warp's Tm column ----
        float acc0 = 0.f, acc1 = 0.f;
        #pragma unroll
        for (int k = 0; k < 16; k += 2) {
            acc0 = fmaf(a[k],     TmS[w * M_TAGS + lane + 32 * k],       acc0);
            acc1 = fmaf(a[k + 1], TmS[w * M_TAGS + lane + 32 * (k + 1)], acc1);
        }
        float acc = acc0 + acc1;
        #pragma unroll
        for (int off = 16; off; off >>= 1)
            acc += __shfl_xor_sync(FULL, acc, off);

        // ---- scaling: 1/128 each step (exact); true renorm every 256 ----
        float scale = 0.0078125f;
        if ((t & 255) == 0) {
            float ss = 0.f;
            #pragma unroll
            for (int k = 0; k < 16; ++k) ss += a[k];
            #pragma unroll
            for (int off = 16; off; off >>= 1)
                ss += __shfl_xor_sync(FULL, ss, off);
            scale = 0.0078125f / ss;                    // identical in all CTAs
            if (cta == 0 && tid == 0) log_acc += logf(ss);
        }

        // ---- publish our column of alpha_t ----
        if (lane == 0) {
            __stcg(&g_abuf[(t & (RING - 1)) * M_TAGS + jg],
                   acc * scale * ext_next);
            __threadfence();
        }
        if (t + 1 < L_SEQ)
            ext_next = __ldg(&g_ext[(t + 1) * M_TAGS + jg]);
        __syncthreads();
        if (tid == 0) atomicAdd(&g_counter, 1u);
    }

    // ---- finalize: logz = log(sum v_final) + 4095*ln128 + sum log(s_r) ----
    if (cta == 0) {
        if (tid == 0) {
            const unsigned tgt = (unsigned)NCTA * (unsigned)L_SEQ;
            while (*(volatile unsigned*)&g_counter < tgt) {}
        }
        __syncthreads();
        if (tid < 32) {
            const float* src = g_abuf + ((L_SEQ - 1) & (RING - 1)) * M_TAGS;
            float ss = 0.f;
            #pragma unroll
            for (int k = 0; k < 16; ++k) ss += __ldcv(src + tid + 32 * k);
            #pragma unroll
            for (int off = 16; off; off >>= 1)
                ss += __shfl_xor_sync(FULL, ss, off);
            if (tid == 0) {
                // ln(128) = 7*ln(2)
                double logz = (double)logf(ss)
                            + 4095.0 * 4.852030263919617
                            + (double)log_acc;
                out[0] = (float)(logz - (double)g_phipath);
            }
        }
    }
}

// =====================================================================
extern "C" void kernel_launch(void* const* d_in, const int* in_sizes, int n_in,
                              void* d_out, int out_size)
{
    const float* T     = (const float*)d_in[0];
    const float* E     = (const float*)d_in[1];
    const float* Eprev = (const float*)d_in[2];
    const float* Enext = (const float*)d_in[3];
    const float* Cap   = (const float*)d_in[4];
    const int*   x     = (const int*)d_in[5];
    const int*   y     = (const int*)d_in[6];
    const int*   upper = (const int*)d_in[7];
    float*       out   = (float*)d_out;
    (void)in_sizes; (void)n_in; (void)out_size;

    const int ext_blocks = (L_SEQ * M_TAGS + 255) / 256;   // 8192
    crf_init_kernel<<<ext_blocks + 2, 256>>>(T, E, Eprev, Enext, Cap, x, y, upper);
    crf_chain_kernel<<<NCTA, MAIN_THREADS>>>(T, out);
}

// round 6
// speedup vs baseline: 2.3601x; 2.3601x over previous
#include <cuda_runtime.h>
#include <math.h>
#include <stdint.h>

#define M_TAGS   512
#define L_SEQ    4096
#define V_VOCAB  50000
#define VP1      50001
#define NCTA     8
#define THREADS  512
#define CPW      4          // columns per warp
#define FULLMASK 0xffffffffu

// ---- device scratch ----
__device__ float g_a0 [M_TAGS];
__device__ float g_ext[L_SEQ * M_TAGS];   // ext[t][j] = E[j, x[t]]
__device__ float g_phipath;

// ---- PTX helpers ----
__device__ __forceinline__ uint32_t smem_u32(const void* p) {
    uint32_t a;
    asm("{ .reg .u64 t; cvta.to.shared.u64 t, %1; cvt.u32.u64 %0, t; }" : "=r"(a) : "l"(p));
    return a;
}
__device__ __forceinline__ uint32_t mapa_u32(uint32_t addr, uint32_t rank) {
    uint32_t r;
    asm("mapa.shared::cluster.u32 %0, %1, %2;" : "=r"(r) : "r"(addr), "r"(rank));
    return r;
}
__device__ __forceinline__ float4 lds_vol_v4(uint32_t a) {
    float4 v;
    asm volatile("ld.volatile.shared.v4.f32 {%0,%1,%2,%3}, [%4];"
                 : "=f"(v.x), "=f"(v.y), "=f"(v.z), "=f"(v.w) : "r"(a));
    return v;
}
__device__ __forceinline__ void sts_vol(uint32_t a, float v) {
    asm volatile("st.volatile.shared.f32 [%0], %1;" :: "r"(a), "f"(v));
}
__device__ __forceinline__ void st_cluster_v4(uint32_t a, float4 v) {
    asm volatile("st.shared::cluster.v4.f32 [%0], {%1,%2,%3,%4};"
                 :: "r"(a), "f"(v.x), "f"(v.y), "f"(v.z), "f"(v.w));
}
__device__ __forceinline__ unsigned long long packdup(float x) {
    unsigned long long d; uint32_t u = __float_as_uint(x);
    asm("mov.b64 %0, {%1, %1};" : "=l"(d) : "r"(u)); return d;
}
__device__ __forceinline__ unsigned long long pack2(float x, float y) {
    unsigned long long d;
    asm("mov.b64 %0, {%1, %2};" : "=l"(d) : "r"(__float_as_uint(x)), "r"(__float_as_uint(y)));
    return d;
}
__device__ __forceinline__ void fma2(unsigned long long& d, unsigned long long a, unsigned long long b) {
    asm("fma.rn.f32x2 %0, %1, %2, %0;" : "+l"(d) : "l"(a), "l"(b));
}
__device__ __forceinline__ void add2(unsigned long long& d, unsigned long long a) {
    asm("add.rn.f32x2 %0, %0, %1;" : "+l"(d) : "l"(a));
}
__device__ __forceinline__ void unpack2(unsigned long long d, float& lo, float& hi) {
    uint32_t a, b;
    asm("mov.b64 {%0, %1}, %2;" : "=r"(a), "=r"(b) : "l"(d));
    lo = __uint_as_float(a); hi = __uint_as_float(b);
}
__device__ __forceinline__ void cluster_barrier() {
    asm volatile("barrier.cluster.arrive.aligned;" ::: "memory");
    asm volatile("barrier.cluster.wait.aligned;"   ::: "memory");
}

// =====================================================================
// Init: alpha0 -> g_a0, phi_path, ext gather
// =====================================================================
__global__ void crf_init_kernel(const float* __restrict__ T,
                                const float* __restrict__ E,
                                const float* __restrict__ Eprev,
                                const float* __restrict__ Enext,
                                const float* __restrict__ Cap,
                                const int*   __restrict__ x,
                                const int*   __restrict__ y,
                                const int*   __restrict__ upper)
{
    const int b   = blockIdx.x;
    const int tid = threadIdx.x;

    if (b == 0) {
        const int x0 = x[0], x1 = x[1], u0 = upper[0];
        for (int m = tid; m < M_TAGS; m += blockDim.x) {
            float phi = T[M_TAGS * M_TAGS + m]
                      + Eprev[m * VP1 + M_TAGS]
                      + Enext[m * VP1 + x1]
                      + Cap[m * 2 + u0]
                      + E[m * V_VOCAB + x0];
            g_a0[m] = expf(phi);
        }
    } else if (b == 1) {
        __shared__ float red[256];
        float acc = 0.f;
        for (int t = tid; t < L_SEQ; t += blockDim.x) {
            int yt = y[t];
            int yp = (t == 0)         ? M_TAGS : y[t - 1];
            int xp = (t == 0)         ? M_TAGS : x[t - 1];
            int xn = (t == L_SEQ - 1) ? M_TAGS : x[t + 1];
            acc += T[yp * M_TAGS + yt]
                 + Eprev[yt * VP1 + xp]
                 + Enext[yt * VP1 + xn]
                 + Cap[yt * 2 + upper[t]]
                 + E[yt * V_VOCAB + x[t]];
        }
        red[tid] = acc;
        __syncthreads();
        for (int s = 128; s > 0; s >>= 1) {
            if (tid < s) red[tid] += red[tid + s];
            __syncthreads();
        }
        if (tid == 0) g_phipath = red[0];
    } else {
        long long idx = (long long)(b - 2) * blockDim.x + tid;
        if (idx < (long long)L_SEQ * M_TAGS) {
            int t = (int)(idx >> 9);
            int j = (int)(idx & 511);
            g_ext[idx] = E[(long long)j * V_VOCAB + x[t]];
        }
    }
}

// =====================================================================
// Chain: one 8-CTA cluster. Full state replicated in each CTA's SMEM
// (4-slot ring). Producers push results to all 8 CTAs via DSMEM.
// Consumers poll LOCAL smem (volatile LDS128) for sentinel -1 -> >=0.
// No atomics, no L2, no barriers in the loop. Trailing cluster barrier
// guarantees no CTA exits while peers still write into its SMEM.
// =====================================================================
__global__ void __launch_bounds__(THREADS, 1) __cluster_dims__(NCTA, 1, 1)
crf_chain_kernel(const float* __restrict__ T, float* __restrict__ out)
{
    __shared__ float A[4][M_TAGS];     // 4-slot ring, 2KB per slot

    const int tid  = threadIdx.x;
    const int w    = tid >> 5;
    const int lane = tid & 31;
    const int rank = blockIdx.x;       // grid == one cluster
    const int c0   = rank * 64 + w * CPW;

    // ---- local init: alpha0 in slot 0, sentinels in slots 1..3 ----
    A[0][tid] = g_a0[tid];
    A[1][tid] = -1.f;
    A[2][tid] = -1.f;
    A[3][tid] = -1.f;
    __syncthreads();
    cluster_barrier();

    // ---- Tm slice into registers (lane-strided k: k = g*32 + lane) ----
    unsigned long long tm01[16], tm23[16];
    #pragma unroll
    for (int g = 0; g < 16; ++g) {
        int k = g * 32 + lane;
        float4 tv = *(const float4*)(T + (long long)k * M_TAGS + c0);
        tm01[g] = pack2(tv.x, tv.y);
        tm23[g] = pack2(tv.z, tv.w);
    }

    // ---- peer SMEM base addresses ----
    const uint32_t abase = smem_u32(&A[0][0]);
    uint32_t peer[NCTA];
    #pragma unroll
    for (int p = 0; p < NCTA; ++p) peer[p] = mapa_u32(abase, (uint32_t)p);

    float4 ext_next = make_float4(0.f, 0.f, 0.f, 0.f);
    if (lane == 0) ext_next = *(const float4*)&g_ext[1 * M_TAGS + c0];
    float log_acc = 0.f;
    int   budget  = 1 << 25;           // fail loudly instead of hanging

    for (int t = 1; t < L_SEQ; ++t) {
        // ---- poll local smem slot (t-1)&3: data is its own flag ----
        const uint32_t rbase = abase + (((t - 1) & 3) << 11) + (lane << 4);
        float4 v0, v1, v2, v3;
        for (;;) {
            v0 = lds_vol_v4(rbase);
            v1 = lds_vol_v4(rbase + 512);
            v2 = lds_vol_v4(rbase + 1024);
            v3 = lds_vol_v4(rbase + 1536);
            bool ok = (v0.x >= 0.f) & (v0.y >= 0.f) & (v0.z >= 0.f) & (v0.w >= 0.f)
                    & (v1.x >= 0.f) & (v1.y >= 0.f) & (v1.z >= 0.f) & (v1.w >= 0.f)
                    & (v2.x >= 0.f) & (v2.y >= 0.f) & (v2.z >= 0.f) & (v2.w >= 0.f)
                    & (v3.x >= 0.f) & (v3.y >= 0.f) & (v3.z >= 0.f) & (v3.w >= 0.f);
            if (__all_sync(FULLMASK, ok)) break;
            if (--budget < 0) break;
        }

        // ---- retire slot (t+2)&3: reset to sentinel (1 word/thread) ----
        sts_vol(abase + (((t + 2) & 3) << 11) + (tid << 2), -1.f);

        // ---- 4 dot products via packed f32x2 FMA ----
        float av[16] = { v0.x, v0.y, v0.z, v0.w,  v1.x, v1.y, v1.z, v1.w,
                         v2.x, v2.y, v2.z, v2.w,  v3.x, v3.y, v3.z, v3.w };
        unsigned long long acc01a = 0ull, acc01b = 0ull, acc23a = 0ull, acc23b = 0ull;
        #pragma unroll
        for (int g = 0; g < 16; g += 2) {
            unsigned long long aa = packdup(av[g]);
            unsigned long long bb = packdup(av[g + 1]);
            fma2(acc01a, aa, tm01[g]);
            fma2(acc23a, aa, tm23[g]);
            fma2(acc01b, bb, tm01[g + 1]);
            fma2(acc23b, bb, tm23[g + 1]);
        }
        add2(acc01a, acc01b);
        add2(acc23a, acc23b);
        float r0, r1, r2, r3;
        unpack2(acc01a, r0, r1);
        unpack2(acc23a, r2, r3);

        // ---- cross-lane reduce (4 interleaved trees) ----
        #pragma unroll
        for (int off = 16; off; off >>= 1) {
            r0 += __shfl_xor_sync(FULLMASK, r0, off);
            r1 += __shfl_xor_sync(FULLMASK, r1, off);
            r2 += __shfl_xor_sync(FULLMASK, r2, off);
            r3 += __shfl_xor_sync(FULLMASK, r3, off);
        }

        // ---- scaling: exact 1/128 per step; true renorm every 256 ----
        float scale = 0.0078125f;
        if ((t & 255) == 0) {
            float ss = 0.f;
            #pragma unroll
            for (int g = 0; g < 16; ++g) ss += av[g];
            #pragma unroll
            for (int off = 16; off; off >>= 1)
                ss += __shfl_xor_sync(FULLMASK, ss, off);
            scale = 0.0078125f / ss;                 // identical in every warp
            if (rank == 0 && tid == 0) log_acc += logf(ss);
        }

        // ---- publish 4 columns to all 8 CTAs (DSMEM) + prefetch ext ----
        if (lane == 0) {
            float4 o;
            o.x = r0 * scale * ext_next.x;
            o.y = r1 * scale * ext_next.y;
            o.z = r2 * scale * ext_next.z;
            o.w = r3 * scale * ext_next.w;
            const uint32_t off = ((t & 3) << 11) + (c0 << 2);
            #pragma unroll
            for (int p = 0; p < NCTA; ++p) st_cluster_v4(peer[p] + off, o);
            if (t + 1 < L_SEQ)
                ext_next = *(const float4*)&g_ext[(long long)(t + 1) * M_TAGS + c0];
        }
    }

    // ---- finalize: rank 0, warp 0 ----
    if (rank == 0 && w == 0) {
        const uint32_t rbase = abase + (((L_SEQ - 1) & 3) << 11) + (lane << 4);
        float4 v0, v1, v2, v3;
        for (;;) {
            v0 = lds_vol_v4(rbase);
            v1 = lds_vol_v4(rbase + 512);
            v2 = lds_vol_v4(rbase + 1024);
            v3 = lds_vol_v4(rbase + 1536);
            bool ok = (v0.x >= 0.f) & (v0.y >= 0.f) & (v0.z >= 0.f) & (v0.w >= 0.f)
                    & (v1.x >= 0.f) & (v1.y >= 0.f) & (v1.z >= 0.f) & (v1.w >= 0.f)
                    & (v2.x >= 0.f) & (v2.y >= 0.f) & (v2.z >= 0.f) & (v2.w >= 0.f)
                    & (v3.x >= 0.f) & (v3.y >= 0.f) & (v3.z >= 0.f) & (v3.w >= 0.f);
            if (__all_sync(FULLMASK, ok)) break;
            if (--budget < 0) break;
        }
        float ss = (v0.x + v0.y) + (v0.z + v0.w)
                 + (v1.x + v1.y) + (v1.z + v1.w)
                 + (v2.x + v2.y) + (v2.z + v2.w)
                 + (v3.x + v3.y) + (v3.z + v3.w);
        #pragma unroll
        for (int off = 16; off; off >>= 1)
            ss += __shfl_xor_sync(FULLMASK, ss, off);
        if (lane == 0) {
            // ln(128) = 7*ln(2) = 4.852030263919617
            double logz = (double)logf(ss)
                        + 4095.0 * 4.852030263919617
                        + (double)log_acc;
            out[0] = (float)(logz - (double)g_phipath);
        }
    }

    // ---- exit fence: no CTA leaves while peers may still write here ----
    cluster_barrier();
}

// =====================================================================
extern "C" void kernel_launch(void* const* d_in, const int* in_sizes, int n_in,
                              void* d_out, int out_size)
{
    const float* T     = (const float*)d_in[0];
    const float* E     = (const float*)d_in[1];
    const float* Eprev = (const float*)d_in[2];
    const float* Enext = (const float*)d_in[3];
    const float* Cap   = (const float*)d_in[4];
    const int*   x     = (const int*)d_in[5];
    const int*   y     = (const int*)d_in[6];
    const int*   upper = (const int*)d_in[7];
    float*       out   = (float*)d_out;
    (void)in_sizes; (void)n_in; (void)out_size;

    const int ext_blocks = (L_SEQ * M_TAGS + 255) / 256;   // 8192
    crf_init_kernel<<<2 + ext_blocks, 256>>>(T, E, Eprev, Enext, Cap, x, y, upper);
    crf_chain_kernel<<<NCTA, THREADS>>>(T, out);
}

// round 7
// speedup vs baseline: 2.4703x; 1.0467x over previous
#include <cuda_runtime.h>
#include <math.h>
#include <stdint.h>

#define M_TAGS   512
#define L_SEQ    4096
#define V_VOCAB  50000
#define VP1      50001
#define NCTA     8
#define THREADS  512
#define CPW      4          // columns per warp
#define FULLMASK 0xffffffffu

// ---- device scratch ----
__device__ float g_a0 [M_TAGS];
__device__ float g_ext[L_SEQ * M_TAGS];   // ext[t][j] = E[j, x[t]]
__device__ float g_phipath;

// ---- PTX helpers ----
__device__ __forceinline__ uint32_t smem_u32(const void* p) {
    uint32_t a;
    asm("{ .reg .u64 t; cvta.to.shared.u64 t, %1; cvt.u32.u64 %0, t; }" : "=r"(a) : "l"(p));
    return a;
}
__device__ __forceinline__ uint32_t mapa_u32(uint32_t addr, uint32_t rank) {
    uint32_t r;
    asm("mapa.shared::cluster.u32 %0, %1, %2;" : "=r"(r) : "r"(addr), "r"(rank));
    return r;
}
__device__ __forceinline__ float4 lds_vol_v4(uint32_t a) {
    float4 v;
    asm volatile("ld.volatile.shared.v4.f32 {%0,%1,%2,%3}, [%4];"
                 : "=f"(v.x), "=f"(v.y), "=f"(v.z), "=f"(v.w) : "r"(a));
    return v;
}
__device__ __forceinline__ void sts_vol(uint32_t a, float v) {
    asm volatile("st.volatile.shared.f32 [%0], %1;" :: "r"(a), "f"(v));
}
__device__ __forceinline__ void st_cluster_v4(uint32_t a, float4 v) {
    asm volatile("st.shared::cluster.v4.f32 [%0], {%1,%2,%3,%4};"
                 :: "r"(a), "f"(v.x), "f"(v.y), "f"(v.z), "f"(v.w));
}
__device__ __forceinline__ unsigned long long packdup(float x) {
    unsigned long long d; uint32_t u = __float_as_uint(x);
    asm("mov.b64 %0, {%1, %1};" : "=l"(d) : "r"(u)); return d;
}
__device__ __forceinline__ unsigned long long pack2(float x, float y) {
    unsigned long long d;
    asm("mov.b64 %0, {%1, %2};" : "=l"(d) : "r"(__float_as_uint(x)), "r"(__float_as_uint(y)));
    return d;
}
__device__ __forceinline__ void fma2(unsigned long long& d, unsigned long long a, unsigned long long b) {
    asm("fma.rn.f32x2 %0, %1, %2, %0;" : "+l"(d) : "l"(a), "l"(b));
}
__device__ __forceinline__ void add2(unsigned long long& d, unsigned long long a) {
    asm("add.rn.f32x2 %0, %0, %1;" : "+l"(d) : "l"(a));
}
__device__ __forceinline__ void unpack2(unsigned long long d, float& lo, float& hi) {
    uint32_t a, b;
    asm("mov.b64 {%0, %1}, %2;" : "=r"(a), "=r"(b) : "l"(d));
    lo = __uint_as_float(a); hi = __uint_as_float(b);
}
__device__ __forceinline__ void cluster_barrier() {
    asm volatile("barrier.cluster.arrive.aligned;" ::: "memory");
    asm volatile("barrier.cluster.wait.aligned;"   ::: "memory");
}

// =====================================================================
// Init: alpha0 -> g_a0, phi_path, ext gather
// =====================================================================
__global__ void crf_init_kernel(const float* __restrict__ T,
                                const float* __restrict__ E,
                                const float* __restrict__ Eprev,
                                const float* __restrict__ Enext,
                                const float* __restrict__ Cap,
                                const int*   __restrict__ x,
                                const int*   __restrict__ y,
                                const int*   __restrict__ upper)
{
    const int b   = blockIdx.x;
    const int tid = threadIdx.x;

    if (b == 0) {
        const int x0 = x[0], x1 = x[1], u0 = upper[0];
        for (int m = tid; m < M_TAGS; m += blockDim.x) {
            float phi = T[M_TAGS * M_TAGS + m]
                      + Eprev[m * VP1 + M_TAGS]
                      + Enext[m * VP1 + x1]
                      + Cap[m * 2 + u0]
                      + E[m * V_VOCAB + x0];
            g_a0[m] = expf(phi);
        }
    } else if (b == 1) {
        __shared__ float red[256];
        float acc = 0.f;
        for (int t = tid; t < L_SEQ; t += blockDim.x) {
            int yt = y[t];
            int yp = (t == 0)         ? M_TAGS : y[t - 1];
            int xp = (t == 0)         ? M_TAGS : x[t - 1];
            int xn = (t == L_SEQ - 1) ? M_TAGS : x[t + 1];
            acc += T[yp * M_TAGS + yt]
                 + Eprev[yt * VP1 + xp]
                 + Enext[yt * VP1 + xn]
                 + Cap[yt * 2 + upper[t]]
                 + E[yt * V_VOCAB + x[t]];
        }
        red[tid] = acc;
        __syncthreads();
        for (int s = 128; s > 0; s >>= 1) {
            if (tid < s) red[tid] += red[tid + s];
            __syncthreads();
        }
        if (tid == 0) g_phipath = red[0];
    } else {
        long long idx = (long long)(b - 2) * blockDim.x + tid;
        if (idx < (long long)L_SEQ * M_TAGS) {
            int t = (int)(idx >> 9);
            int j = (int)(idx & 511);
            g_ext[idx] = E[(long long)j * V_VOCAB + x[t]];
        }
    }
}

// =====================================================================
// Chain: one 8-CTA cluster, 4-slot SMEM ring replicated per CTA.
// Poll: since each producer warp writes its 4 columns with ONE 128-bit
// cluster store (single-access atomic), checking .x of each float4 is
// sufficient. Publish: lanes 0-7 store to the 8 peers in ONE SIMT op.
// =====================================================================
__global__ void __launch_bounds__(THREADS, 1) __cluster_dims__(NCTA, 1, 1)
crf_chain_kernel(const float* __restrict__ T, float* __restrict__ out)
{
    __shared__ float A[4][M_TAGS];     // 4-slot ring, 2KB per slot

    const int tid  = threadIdx.x;
    const int w    = tid >> 5;
    const int lane = tid & 31;
    const int rank = blockIdx.x;       // grid == one cluster
    const int c0   = rank * 64 + w * CPW;

    // ---- local init: alpha0 in slot 0, sentinels in slots 1..3 ----
    A[0][tid] = g_a0[tid];
    A[1][tid] = -1.f;
    A[2][tid] = -1.f;
    A[3][tid] = -1.f;
    __syncthreads();
    cluster_barrier();

    // ---- Tm slice into registers (lane-strided k: k = g*32 + lane) ----
    unsigned long long tm01[16], tm23[16];
    #pragma unroll
    for (int g = 0; g < 16; ++g) {
        int k = g * 32 + lane;
        float4 tv = *(const float4*)(T + (long long)k * M_TAGS + c0);
        tm01[g] = pack2(tv.x, tv.y);
        tm23[g] = pack2(tv.z, tv.w);
    }

    // ---- per-lane peer address: lane p (p<8) targets cluster rank p ----
    const uint32_t abase  = smem_u32(&A[0][0]);
    const uint32_t mypeer = mapa_u32(abase, (uint32_t)(lane & 7));
    const uint32_t col_off = (uint32_t)(c0 << 2);

    float4 ext_next = *(const float4*)&g_ext[1 * M_TAGS + c0];  // broadcast
    float log_acc = 0.f;
    int   budget  = 1 << 25;           // fail loudly instead of hanging

    for (int t = 1; t < L_SEQ; ++t) {
        // ---- poll local smem slot (t-1)&3: .x of each 16B group ----
        const uint32_t rbase = abase + (((t - 1) & 3) << 11) + (lane << 4);
        float4 v0, v1, v2, v3;
        for (;;) {
            v0 = lds_vol_v4(rbase);
            v1 = lds_vol_v4(rbase + 512);
            v2 = lds_vol_v4(rbase + 1024);
            v3 = lds_vol_v4(rbase + 1536);
            float m = fminf(fminf(v0.x, v1.x), fminf(v2.x, v3.x));
            if (__all_sync(FULLMASK, m >= 0.f)) break;
            if (--budget < 0) break;
        }

        // ---- retire slot (t+2)&3: reset to sentinel (1 word/thread) ----
        sts_vol(abase + (((t + 2) & 3) << 11) + (tid << 2), -1.f);

        // ---- 4 dot products via packed f32x2 FMA ----
        float av[16] = { v0.x, v0.y, v0.z, v0.w,  v1.x, v1.y, v1.z, v1.w,
                         v2.x, v2.y, v2.z, v2.w,  v3.x, v3.y, v3.z, v3.w };
        unsigned long long acc01a = 0ull, acc01b = 0ull, acc23a = 0ull, acc23b = 0ull;
        #pragma unroll
        for (int g = 0; g < 16; g += 2) {
            unsigned long long aa = packdup(av[g]);
            unsigned long long bb = packdup(av[g + 1]);
            fma2(acc01a, aa, tm01[g]);
            fma2(acc23a, aa, tm23[g]);
            fma2(acc01b, bb, tm01[g + 1]);
            fma2(acc23b, bb, tm23[g + 1]);
        }
        add2(acc01a, acc01b);
        add2(acc23a, acc23b);
        float r0, r1, r2, r3;
        unpack2(acc01a, r0, r1);
        unpack2(acc23a, r2, r3);

        // ---- cross-lane reduce (4 interleaved trees, result in all lanes)
        #pragma unroll
        for (int off = 16; off; off >>= 1) {
            r0 += __shfl_xor_sync(FULLMASK, r0, off);
            r1 += __shfl_xor_sync(FULLMASK, r1, off);
            r2 += __shfl_xor_sync(FULLMASK, r2, off);
            r3 += __shfl_xor_sync(FULLMASK, r3, off);
        }

        // ---- scaling: exact 1/128 per step; true renorm every 256 ----
        float scale = 0.0078125f;
        if ((t & 255) == 0) {
            float ss = 0.f;
            #pragma unroll
            for (int g = 0; g < 16; ++g) ss += av[g];
            #pragma unroll
            for (int off = 16; off; off >>= 1)
                ss += __shfl_xor_sync(FULLMASK, ss, off);
            scale = 0.0078125f / ss;                 // identical in every warp
            if (rank == 0 && tid == 0) log_acc += logf(ss);
        }

        // ---- publish 4 columns to all 8 CTAs in ONE SIMT store ----
        float4 o;
        o.x = r0 * scale * ext_next.x;
        o.y = r1 * scale * ext_next.y;
        o.z = r2 * scale * ext_next.z;
        o.w = r3 * scale * ext_next.w;
        if (lane < 8)
            st_cluster_v4(mypeer + ((t & 3) << 11) + col_off, o);
        if (t + 1 < L_SEQ)
            ext_next = *(const float4*)&g_ext[(long long)(t + 1) * M_TAGS + c0];
    }

    // ---- finalize: rank 0, warp 0 ----
    if (rank == 0 && w == 0) {
        const uint32_t rbase = abase + (((L_SEQ - 1) & 3) << 11) + (lane << 4);
        float4 v0, v1, v2, v3;
        for (;;) {
            v0 = lds_vol_v4(rbase);
            v1 = lds_vol_v4(rbase + 512);
            v2 = lds_vol_v4(rbase + 1024);
            v3 = lds_vol_v4(rbase + 1536);
            float m = fminf(fminf(v0.x, v1.x), fminf(v2.x, v3.x));
            if (__all_sync(FULLMASK, m >= 0.f)) break;
            if (--budget < 0) break;
        }
        float ss = (v0.x + v0.y) + (v0.z + v0.w)
                 + (v1.x + v1.y) + (v1.z + v1.w)
                 + (v2.x + v2.y) + (v2.z + v2.w)
                 + (v3.x + v3.y) + (v3.z + v3.w);
        #pragma unroll
        for (int off = 16; off; off >>= 1)
            ss += __shfl_xor_sync(FULLMASK, ss, off);
        if (lane == 0) {
            // ln(128) = 7*ln(2) = 4.852030263919617
            double logz = (double)logf(ss)
                        + 4095.0 * 4.852030263919617
                        + (double)log_acc;
            out[0] = (float)(logz - (double)g_phipath);
        }
    }

    // ---- exit fence: no CTA leaves while peers may still write here ----
    cluster_barrier();
}

// =====================================================================
extern "C" void kernel_launch(void* const* d_in, const int* in_sizes, int n_in,
                              void* d_out, int out_size)
{
    const float* T     = (const float*)d_in[0];
    const float* E     = (const float*)d_in[1];
    const float* Eprev = (const float*)d_in[2];
    const float* Enext = (const float*)d_in[3];
    const float* Cap   = (const float*)d_in[4];
    const int*   x     = (const int*)d_in[5];
    const int*   y     = (const int*)d_in[6];
    const int*   upper = (const int*)d_in[7];
    float*       out   = (float*)d_out;
    (void)in_sizes; (void)n_in; (void)out_size;

    const int ext_blocks = (L_SEQ * M_TAGS + 255) / 256;   // 8192
    crf_init_kernel<<<2 + ext_blocks, 256>>>(T, E, Eprev, Enext, Cap, x, y, upper);
    crf_chain_kernel<<<NCTA, THREADS>>>(T, out);
}

// round 8
// speedup vs baseline: 3.5344x; 1.4307x over previous
#include <cuda_runtime.h>
#include <math.h>
#include <stdint.h>

#define M_TAGS   512
#define L_SEQ    4096
#define V_VOCAB  50000
#define VP1      50001
#define NCTA     16
#define THREADS  256
#define CPW      4          // columns per warp
#define FULLMASK 0xffffffffu

// ---- device scratch ----
__device__ float g_a0 [M_TAGS];
__device__ float g_ext[L_SEQ * M_TAGS];   // ext[t][j] = E[j, x[t]]
__device__ float g_phipath;

// ---- PTX helpers ----
__device__ __forceinline__ uint32_t smem_u32(const void* p) {
    uint32_t a;
    asm("{ .reg .u64 t; cvta.to.shared.u64 t, %1; cvt.u32.u64 %0, t; }" : "=r"(a) : "l"(p));
    return a;
}
__device__ __forceinline__ uint32_t mapa_u32(uint32_t addr, uint32_t rank) {
    uint32_t r;
    asm("mapa.shared::cluster.u32 %0, %1, %2;" : "=r"(r) : "r"(addr), "r"(rank));
    return r;
}
__device__ __forceinline__ float lds_vol_f32(uint32_t a) {
    float v;
    asm volatile("ld.volatile.shared.f32 %0, [%1];" : "=f"(v) : "r"(a));
    return v;
}
__device__ __forceinline__ float4 lds_vol_v4(uint32_t a) {
    float4 v;
    asm volatile("ld.volatile.shared.v4.f32 {%0,%1,%2,%3}, [%4];"
                 : "=f"(v.x), "=f"(v.y), "=f"(v.z), "=f"(v.w) : "r"(a));
    return v;
}
__device__ __forceinline__ void sts_vol(uint32_t a, float v) {
    asm volatile("st.volatile.shared.f32 [%0], %1;" :: "r"(a), "f"(v));
}
__device__ __forceinline__ void st_cluster_v4(uint32_t a, float4 v) {
    asm volatile("st.shared::cluster.v4.f32 [%0], {%1,%2,%3,%4};"
                 :: "r"(a), "f"(v.x), "f"(v.y), "f"(v.z), "f"(v.w));
}
__device__ __forceinline__ unsigned long long packdup(float x) {
    unsigned long long d; uint32_t u = __float_as_uint(x);
    asm("mov.b64 %0, {%1, %1};" : "=l"(d) : "r"(u)); return d;
}
__device__ __forceinline__ unsigned long long pack2(float x, float y) {
    unsigned long long d;
    asm("mov.b64 %0, {%1, %2};" : "=l"(d) : "r"(__float_as_uint(x)), "r"(__float_as_uint(y)));
    return d;
}
__device__ __forceinline__ void fma2(unsigned long long& d, unsigned long long a, unsigned long long b) {
    asm("fma.rn.f32x2 %0, %1, %2, %0;" : "+l"(d) : "l"(a), "l"(b));
}
__device__ __forceinline__ void add2(unsigned long long& d, unsigned long long a) {
    asm("add.rn.f32x2 %0, %0, %1;" : "+l"(d) : "l"(a));
}
__device__ __forceinline__ void unpack2(unsigned long long d, float& lo, float& hi) {
    uint32_t a, b;
    asm("mov.b64 {%0, %1}, %2;" : "=r"(a), "=r"(b) : "l"(d));
    lo = __uint_as_float(a); hi = __uint_as_float(b);
}
__device__ __forceinline__ void cluster_barrier() {
    asm volatile("barrier.cluster.arrive.aligned;" ::: "memory");
    asm volatile("barrier.cluster.wait.aligned;"   ::: "memory");
}

// =====================================================================
// Init: alpha0 -> g_a0, phi_path, ext gather
// =====================================================================
__global__ void crf_init_kernel(const float* __restrict__ T,
                                const float* __restrict__ E,
                                const float* __restrict__ Eprev,
                                const float* __restrict__ Enext,
                                const float* __restrict__ Cap,
                                const int*   __restrict__ x,
                                const int*   __restrict__ y,
                                const int*   __restrict__ upper)
{
    const int b   = blockIdx.x;
    const int tid = threadIdx.x;

    if (b == 0) {
        const int x0 = x[0], x1 = x[1], u0 = upper[0];
        for (int m = tid; m < M_TAGS; m += blockDim.x) {
            float phi = T[M_TAGS * M_TAGS + m]
                      + Eprev[m * VP1 + M_TAGS]
                      + Enext[m * VP1 + x1]
                      + Cap[m * 2 + u0]
                      + E[m * V_VOCAB + x0];
            g_a0[m] = expf(phi);
        }
    } else if (b == 1) {
        __shared__ float red[256];
        float acc = 0.f;
        for (int t = tid; t < L_SEQ; t += blockDim.x) {
            int yt = y[t];
            int yp = (t == 0)         ? M_TAGS : y[t - 1];
            int xp = (t == 0)         ? M_TAGS : x[t - 1];
            int xn = (t == L_SEQ - 1) ? M_TAGS : x[t + 1];
            acc += T[yp * M_TAGS + yt]
                 + Eprev[yt * VP1 + xp]
                 + Enext[yt * VP1 + xn]
                 + Cap[yt * 2 + upper[t]]
                 + E[yt * V_VOCAB + x[t]];
        }
        red[tid] = acc;
        __syncthreads();
        for (int s = 128; s > 0; s >>= 1) {
            if (tid < s) red[tid] += red[tid + s];
            __syncthreads();
        }
        if (tid == 0) g_phipath = red[0];
    } else {
        long long idx = (long long)(b - 2) * blockDim.x + tid;
        if (idx < (long long)L_SEQ * M_TAGS) {
            int t = (int)(idx >> 9);
            int j = (int)(idx & 511);
            g_ext[idx] = E[(long long)j * V_VOCAB + x[t]];
        }
    }
}

// =====================================================================
// Chain: one 16-CTA cluster (nonportable), 256 threads/CTA, 4 cols/warp.
// 4-slot sentinel ring replicated in every CTA's SMEM.
// Detect: scalar volatile LDS of .x per 16B group (producer writes the
// group with ONE atomic 128-bit cluster store). Data fetched once after
// detect. Publish: lanes 0-15 store to the 16 peers in ONE SIMT op.
// =====================================================================
__global__ void __launch_bounds__(THREADS, 1) __cluster_dims__(NCTA, 1, 1)
crf_chain_kernel(const float* __restrict__ T, float* __restrict__ out)
{
    __shared__ float A[4][M_TAGS];     // 4-slot ring, 2KB per slot

    const int tid  = threadIdx.x;
    const int w    = tid >> 5;
    const int lane = tid & 31;
    const int rank = blockIdx.x;       // grid == one cluster
    const int c0   = rank * 32 + w * CPW;

    // ---- local init: alpha0 in slot 0, sentinels in slots 1..3 ----
    A[0][tid]       = g_a0[tid];
    A[0][tid + 256] = g_a0[tid + 256];
    A[1][tid]       = -1.f;  A[1][tid + 256] = -1.f;
    A[2][tid]       = -1.f;  A[2][tid + 256] = -1.f;
    A[3][tid]       = -1.f;  A[3][tid + 256] = -1.f;
    __syncthreads();
    cluster_barrier();

    // ---- Tm slice into registers (lane-strided k: k = g*32 + lane) ----
    unsigned long long tm01[16], tm23[16];
    #pragma unroll
    for (int g = 0; g < 16; ++g) {
        int k = g * 32 + lane;
        float4 tv = *(const float4*)(T + (long long)k * M_TAGS + c0);
        tm01[g] = pack2(tv.x, tv.y);
        tm23[g] = pack2(tv.z, tv.w);
    }

    // ---- per-lane peer address: lane p (p<16) targets cluster rank p ----
    const uint32_t abase   = smem_u32(&A[0][0]);
    const uint32_t mypeer  = mapa_u32(abase, (uint32_t)(lane & 15));
    const uint32_t col_off = (uint32_t)(c0 << 2);

    float4 ext_next = *(const float4*)&g_ext[1 * M_TAGS + c0];  // broadcast
    float log_acc = 0.f;
    int   budget  = 1 << 25;           // fail loudly instead of hanging

    for (int t = 1; t < L_SEQ; ++t) {
        // ---- detect slot (t-1)&3: scalar poll of each group's .x ----
        const uint32_t rbase = abase + (((t - 1) & 3) << 11) + (lane << 4);
        for (;;) {
            float m0 = lds_vol_f32(rbase);
            float m1 = lds_vol_f32(rbase + 512);
            float m2 = lds_vol_f32(rbase + 1024);
            float m3 = lds_vol_f32(rbase + 1536);
            float m  = fminf(fminf(m0, m1), fminf(m2, m3));
            if (__all_sync(FULLMASK, m >= 0.f)) break;
            if (--budget < 0) break;
        }
        // ---- fetch data once (volatile v4; groups are store-atomic) ----
        float4 v0 = lds_vol_v4(rbase);
        float4 v1 = lds_vol_v4(rbase + 512);
        float4 v2 = lds_vol_v4(rbase + 1024);
        float4 v3 = lds_vol_v4(rbase + 1536);

        // ---- retire slot (t+2)&3: reset to sentinel (2 words/thread) ----
        {
            const uint32_t sb = abase + (((t + 2) & 3) << 11);
            sts_vol(sb + (tid << 2), -1.f);
            sts_vol(sb + ((tid + 256) << 2), -1.f);
        }

        // ---- 4 dot products via packed f32x2 FMA ----
        float av[16] = { v0.x, v0.y, v0.z, v0.w,  v1.x, v1.y, v1.z, v1.w,
                         v2.x, v2.y, v2.z, v2.w,  v3.x, v3.y, v3.z, v3.w };
        unsigned long long acc01a = 0ull, acc01b = 0ull, acc23a = 0ull, acc23b = 0ull;
        #pragma unroll
        for (int g = 0; g < 16; g += 2) {
            unsigned long long aa = packdup(av[g]);
            unsigned long long bb = packdup(av[g + 1]);
            fma2(acc01a, aa, tm01[g]);
            fma2(acc23a, aa, tm23[g]);
            fma2(acc01b, bb, tm01[g + 1]);
            fma2(acc23b, bb, tm23[g + 1]);
        }
        add2(acc01a, acc01b);
        add2(acc23a, acc23b);
        float r0, r1, r2, r3;
        unpack2(acc01a, r0, r1);
        unpack2(acc23a, r2, r3);

        // ---- cross-lane reduce (4 interleaved trees, result in all lanes)
        #pragma unroll
        for (int off = 16; off; off >>= 1) {
            r0 += __shfl_xor_sync(FULLMASK, r0, off);
            r1 += __shfl_xor_sync(FULLMASK, r1, off);
            r2 += __shfl_xor_sync(FULLMASK, r2, off);
            r3 += __shfl_xor_sync(FULLMASK, r3, off);
        }

        // ---- scaling: exact 1/128 per step; true renorm every 256 ----
        float scale = 0.0078125f;
        if ((t & 255) == 0) {
            float ss = 0.f;
            #pragma unroll
            for (int g = 0; g < 16; ++g) ss += av[g];
            #pragma unroll
            for (int off = 16; off; off >>= 1)
                ss += __shfl_xor_sync(FULLMASK, ss, off);
            scale = 0.0078125f / ss;                 // identical in every warp
            if (rank == 0 && tid == 0) log_acc += logf(ss);
        }

        // ---- publish 4 columns to all 16 CTAs in ONE SIMT store ----
        float4 o;
        o.x = r0 * scale * ext_next.x;
        o.y = r1 * scale * ext_next.y;
        o.z = r2 * scale * ext_next.z;
        o.w = r3 * scale * ext_next.w;
        if (lane < 16)
            st_cluster_v4(mypeer + ((t & 3) << 11) + col_off, o);
        if (t + 1 < L_SEQ)
            ext_next = *(const float4*)&g_ext[(long long)(t + 1) * M_TAGS + c0];
    }

    // ---- finalize: rank 0, warp 0 ----
    if (rank == 0 && w == 0) {
        const uint32_t rbase = abase + (((L_SEQ - 1) & 3) << 11) + (lane << 4);
        float4 v0, v1, v2, v3;
        for (;;) {
            float m0 = lds_vol_f32(rbase);
            float m1 = lds_vol_f32(rbase + 512);
            float m2 = lds_vol_f32(rbase + 1024);
            float m3 = lds_vol_f32(rbase + 1536);
            float m  = fminf(fminf(m0, m1), fminf(m2, m3));
            if (__all_sync(FULLMASK, m >= 0.f)) break;
            if (--budget < 0) break;
        }
        v0 = lds_vol_v4(rbase);
        v1 = lds_vol_v4(rbase + 512);
        v2 = lds_vol_v4(rbase + 1024);
        v3 = lds_vol_v4(rbase + 1536);
        float ss = (v0.x + v0.y) + (v0.z + v0.w)
                 + (v1.x + v1.y) + (v1.z + v1.w)
                 + (v2.x + v2.y) + (v2.z + v2.w)
                 + (v3.x + v3.y) + (v3.z + v3.w);
        #pragma unroll
        for (int off = 16; off; off >>= 1)
            ss += __shfl_xor_sync(FULLMASK, ss, off);
        if (lane == 0) {
            // ln(128) = 7*ln(2) = 4.852030263919617
            double logz = (double)logf(ss)
                        + 4095.0 * 4.852030263919617
                        + (double)log_acc;
            out[0] = (float)(logz - (double)g_phipath);
        }
    }

    // ---- exit fence: no CTA leaves while peers may still write here ----
    cluster_barrier();
}

// =====================================================================
extern "C" void kernel_launch(void* const* d_in, const int* in_sizes, int n_in,
                              void* d_out, int out_size)
{
    const float* T     = (const float*)d_in[0];
    const float* E     = (const float*)d_in[1];
    const float* Eprev = (const float*)d_in[2];
    const float* Enext = (const float*)d_in[3];
    const float* Cap   = (const float*)d_in[4];
    const int*   x     = (const int*)d_in[5];
    const int*   y     = (const int*)d_in[6];
    const int*   upper = (const int*)d_in[7];
    float*       out   = (float*)d_out;
    (void)in_sizes; (void)n_in; (void)out_size;

    // allow the 16-CTA (nonportable) cluster
    cudaFuncSetAttribute(crf_chain_kernel,
                         cudaFuncAttributeNonPortableClusterSizeAllowed, 1);

    const int ext_blocks = (L_SEQ * M_TAGS + 255) / 256;   // 8192
    crf_init_kernel<<<2 + ext_blocks, 256>>>(T, E, Eprev, Enext, Cap, x, y, upper);
    crf_chain_kernel<<<NCTA, THREADS>>>(T, out);
}